// round 14
// baseline (speedup 1.0000x reference)
#include <cuda_runtime.h>
#include <cuda_fp16.h>
#include <stdint.h>

#define Bv 4
#define Tv 2048
#define Cv 1024
#define Hv 16
#define HSv 64
#define Mv (Bv*Tv)   /* 8192 */
#define NC 16        /* K=1024 / BK=64 */

// ---------------------------------------------------------------------------
// Static device scratch (no runtime allocation) — all 1-term fp16
// ---------------------------------------------------------------------------
__device__ __half g_xh[(size_t)Mv*Cv];                 // x fp16
__device__ __half g_ch[(size_t)Mv*Cv];                 // combo fp16
__device__ __half g_wt[(size_t)3*Hv*HSv*Cv];           // W^T fp16 (mat0 pre-scaled)
__device__ __half g_wp[(size_t)Cv*Cv];                 // Wproj fp16
__device__ __half g_qh[(size_t)Bv*Hv*Tv*HSv];
__device__ __half g_kh[(size_t)Bv*Hv*Tv*HSv];
__device__ __half g_vh[(size_t)Bv*Hv*Tv*HSv];

// ---------------------------------------------------------------------------
// Helpers
// ---------------------------------------------------------------------------
__device__ __forceinline__ uint32_t smem_u32(const void* p) {
    uint32_t a;
    asm("{ .reg .u64 t; cvta.to.shared.u64 t, %1; cvt.u32.u64 %0, t; }" : "=r"(a) : "l"(p));
    return a;
}
__device__ __forceinline__ void ldm_x4(uint32_t* r, uint32_t a) {
    asm volatile("ldmatrix.sync.aligned.m8n8.x4.shared.b16 {%0,%1,%2,%3}, [%4];"
        : "=r"(r[0]), "=r"(r[1]), "=r"(r[2]), "=r"(r[3]) : "r"(a));
}
__device__ __forceinline__ void ldm_x4t(uint32_t* r, uint32_t a) {
    asm volatile("ldmatrix.sync.aligned.m8n8.x4.trans.shared.b16 {%0,%1,%2,%3}, [%4];"
        : "=r"(r[0]), "=r"(r[1]), "=r"(r[2]), "=r"(r[3]) : "r"(a));
}
__device__ __forceinline__ void mma16816(float* d, const uint32_t* a, const uint32_t* b) {
    asm volatile(
        "mma.sync.aligned.m16n8k16.row.col.f32.f16.f16.f32 "
        "{%0,%1,%2,%3}, {%4,%5,%6,%7}, {%8,%9}, {%0,%1,%2,%3};"
        : "+f"(d[0]), "+f"(d[1]), "+f"(d[2]), "+f"(d[3])
        : "r"(a[0]), "r"(a[1]), "r"(a[2]), "r"(a[3]), "r"(b[0]), "r"(b[1]));
}
#define CP_ASYNC(dst, src) \
    asm volatile("cp.async.cg.shared.global [%0], [%1], 16;" :: "r"(dst), "l"(src) : "memory")
#define CP_COMMIT() asm volatile("cp.async.commit_group;" ::: "memory")
#define CP_WAIT1()  asm volatile("cp.async.wait_group 1;" ::: "memory")
#define CP_WAIT0()  asm volatile("cp.async.wait_group 0;" ::: "memory")

// ---------------------------------------------------------------------------
// Truncate fp32 -> fp16
// ---------------------------------------------------------------------------
__global__ void trunc_kernel(const float* __restrict__ src, __half* __restrict__ dst, int n4)
{
    int i = blockIdx.x * blockDim.x + threadIdx.x;
    if (i >= n4) return;
    float4 v = ((const float4*)src)[i];
    __half2* dp = (__half2*)dst;
    dp[2*i]   = __floats2half2_rn(v.x, v.y);
    dp[2*i+1] = __floats2half2_rn(v.z, v.w);
}

// ---------------------------------------------------------------------------
// Transpose + truncate Wq/Wk/Wv: W[h][c][d] -> Wt[mat][h][d][c]  (fp16)
// Wq pre-scaled by 0.125.
// ---------------------------------------------------------------------------
__global__ __launch_bounds__(256) void wtrans_kernel(
    const float* __restrict__ Wq, const float* __restrict__ Wk, const float* __restrict__ Wv)
{
    __shared__ float ts[64][65];
    const int c0 = blockIdx.x * 64;
    const int h  = blockIdx.y;
    const int mat = blockIdx.z;
    const float* W = (mat == 0) ? Wq : (mat == 1 ? Wk : Wv);
    const float scl = (mat == 0) ? 0.125f : 1.0f;
    const int tid = threadIdx.x;

    #pragma unroll
    for (int i = 0; i < 16; i++) {
        int idx = tid + i * 256;
        int r = idx >> 6, d = idx & 63;
        ts[r][d] = W[(size_t)h * (Cv * HSv) + (size_t)(c0 + r) * HSv + d] * scl;
    }
    __syncthreads();
    #pragma unroll
    for (int i = 0; i < 16; i++) {
        int idx = tid + i * 256;
        int dd = idx >> 6, cc = idx & 63;
        g_wt[((size_t)(mat * Hv + h) * HSv + dd) * Cv + c0 + cc] = __float2half_rn(ts[cc][dd]);
    }
}

// ---------------------------------------------------------------------------
// fp16 1-term GEMM on mma.sync with intra-warp fragment double-buffering.
// MODE 0: QKV -> q/k/v fp16 (b,h,t,d).   MODE 1: proj -> fp32 out + bias.
// CTA 128x128, BK=64, 8 warps (2x4), warp tile 64x32, 3-stage cp.async,
// single barrier per chunk. occ 1 (reg budget for double frag buffers).
// smem/stage (36864 B): A | B, each 128 rows x 144B.
// ---------------------------------------------------------------------------
template<int MODE>
__global__ __launch_bounds__(256, 1) void gemm_kernel(const float* __restrict__ bias,
                                                      float* __restrict__ outp)
{
    extern __shared__ char smem[];
    const uint32_t sb = smem_u32(smem);
    const int tid = threadIdx.x, lane = tid & 31, wid = tid >> 5;
    const int wm = wid & 1, wn = wid >> 1;         // 2x4 warp grid
    const int nb = blockIdx.x, m0 = blockIdx.y * 128, mat = blockIdx.z;

    const __half *am, *bm;
    if (MODE == 0) {
        am = g_xh;
        bm = g_wt + (size_t)mat * (Hv * HSv * Cv);
    } else {
        am = g_ch;
        bm = g_wp;
    }

    // loader: 2048 16B slots per stage (2 tiles x 128 rows x 8), 8 per thread
    auto issue = [&](int c, int stg) {
        const int kc0 = c * 64;
        const uint32_t sbase = sb + (uint32_t)stg * 36864u;
        #pragma unroll
        for (int i = 0; i < 8; i++) {
            int s = tid + i * 256;
            int ms = s >> 10, r = (s >> 3) & 127, c8 = s & 7;
            const __half* src = ms ? bm : am;
            int row = (ms ? nb * 128 : m0) + r;
            const void* g = src + (size_t)row * Cv + kc0 + c8 * 8;
            uint32_t d = sbase + (uint32_t)ms * 18432u + (uint32_t)(r * 144 + c8 * 16);
            CP_ASYNC(d, g);
        }
        CP_COMMIT();
    };

    issue(0, 0);
    issue(1, 1);

    float acc[4][4][4] = {};   // warp tile 64x32

    // per-ks fragment base offsets (lane-dependent, ks-invariant parts)
    const int arow = (lane & 7) + ((lane >> 3) & 1) * 8;
    const int ahalf = (lane >> 4) * 8;
    const int brow = (lane & 7) + ((lane >> 4) & 1) * 8;
    const int bhalf = ((lane >> 3) & 1) * 8;

    uint32_t af[2][4][4], bf[2][2][4];

    auto load_frags = [&](uint32_t stg, int ks, int buf) {
        const int acol = ks * 16 + ahalf;
        #pragma unroll
        for (int mt = 0; mt < 4; mt++) {
            uint32_t off = (uint32_t)((wm * 64 + mt * 16 + arow) * 144 + acol * 2);
            ldm_x4(af[buf][mt], stg + off);
        }
        const int bcol = ks * 16 + bhalf;
        #pragma unroll
        for (int ntp = 0; ntp < 2; ntp++) {
            uint32_t off = (uint32_t)(
                (wn * 32 + ntp * 16 + brow) * 144 + bcol * 2);
            ldm_x4(bf[buf][ntp], stg + 18432u + off);
        }
    };

    for (int c = 0; c < NC; c++) {
        if (c + 1 < NC) CP_WAIT1(); else CP_WAIT0();
        __syncthreads();                       // stage c ready; stage (c-1)%3 drained
        if (c + 2 < NC) issue(c + 2, (c + 2) % 3);
        const uint32_t stg = sb + (uint32_t)(c % 3) * 36864u;

        load_frags(stg, 0, 0);
        #pragma unroll
        for (int ks = 0; ks < 4; ks++) {
            const int cur = ks & 1, nxt = cur ^ 1;
            if (ks < 3) load_frags(stg, ks + 1, nxt);
            #pragma unroll
            for (int mt = 0; mt < 4; mt++)
                #pragma unroll
                for (int ntp = 0; ntp < 2; ntp++) {
                    mma16816(acc[mt][2*ntp],   af[cur][mt], bf[cur][ntp]);
                    mma16816(acc[mt][2*ntp+1], af[cur][mt], bf[cur][ntp] + 2);
                }
        }
    }

    const int g = lane >> 2, tig = lane & 3;
    #pragma unroll
    for (int mt = 0; mt < 4; mt++) {
        const int r0 = m0 + wm * 64 + mt * 16 + g;
        const int r1 = r0 + 8;
        #pragma unroll
        for (int nt = 0; nt < 4; nt++) {
            const int n = nb * 128 + wn * 32 + nt * 8 + tig * 2;
            if (MODE == 0) {
                const int h = n >> 6, dd = n & 63;
                int b0 = r0 >> 11, t0 = r0 & (Tv - 1);
                int b1 = r1 >> 11, t1 = r1 & (Tv - 1);
                size_t i0 = (((size_t)(b0 * Hv + h)) * Tv + t0) * HSv + dd;
                size_t i1 = (((size_t)(b1 * Hv + h)) * Tv + t1) * HSv + dd;
                __half* dst = (mat == 0) ? g_qh : (mat == 1) ? g_kh : g_vh;
                *(__half2*)&dst[i0] = __floats2half2_rn(acc[mt][nt][0], acc[mt][nt][1]);
                *(__half2*)&dst[i1] = __floats2half2_rn(acc[mt][nt][2], acc[mt][nt][3]);
            } else {
                float2 bv = *(const float2*)&bias[n];
                *(float2*)&outp[(size_t)r0 * Cv + n] =
                    make_float2(acc[mt][nt][0] + bv.x, acc[mt][nt][1] + bv.y);
                *(float2*)&outp[(size_t)r1 * Cv + n] =
                    make_float2(acc[mt][nt][2] + bv.x, acc[mt][nt][3] + bv.y);
            }
        }
    }
}

// ---------------------------------------------------------------------------
// fp16 HMMA causal flash attention (all 1-term; unchanged from R13).
// CTA = 128 queries, 8 warps x 16 rows. KV tiles 64, 3-stage cp.async,
// single barrier per tile.
// smem: [3 stages][2 tiles: K,V][64 rows x 144B] = 55296 B
// ---------------------------------------------------------------------------
__global__ __launch_bounds__(256) void flash_kernel()
{
    extern __shared__ char smem[];
    const uint32_t sb = smem_u32(smem);
    const int tid = threadIdx.x, lane = tid & 31, w = tid >> 5;
    const int bx = blockIdx.x, bh = blockIdx.y;
    const int q0 = bx * 128;
    const int qb = q0 + w * 16;
    const int g = lane >> 2, tig = lane & 3;

    // ---- stage Q (fp16, 128 rows -> first 18432 B) ----
    {
        #pragma unroll
        for (int i = 0; i < 4; i++) {
            int s = tid + i * 256;
            int r = s >> 3, c = s & 7;
            const void* gp = g_qh + ((size_t)bh * Tv + q0 + r) * 64 + c * 8;
            uint32_t d = sb + (uint32_t)((r >= 64) ? 9216 : 0)
                       + (uint32_t)((r & 63) * 144 + c * 16);
            CP_ASYNC(d, gp);
        }
        CP_COMMIT(); CP_WAIT0();
        __syncthreads();
    }
    uint32_t qh[4][4];
    {
        const int row = w * 16 + (lane & 15);
        const uint32_t hb = sb + ((row >= 64) ? 9216u : 0u);
        const int rl = row & 63;
        #pragma unroll
        for (int ks = 0; ks < 4; ks++) {
            uint32_t off = (uint32_t)(rl * 144 + (ks * 16 + (lane >> 4) * 8) * 2);
            ldm_x4(qh[ks], hb + off);
        }
    }
    __syncthreads();

    float acc[8][4] = {};
    float m0 = -1e30f, m1 = -1e30f, l0 = 0.0f, l1 = 0.0f;
    const int ntl = 2 * bx + 2;

    auto issueKV = [&](int jt, int stg) {
        const int kv0 = jt * 64;
        #pragma unroll
        for (int i = 0; i < 4; i++) {
            int s = tid + i * 256;
            int tile = s >> 9, r = (s >> 3) & 63, c = s & 7;
            const __half* src = tile ? g_vh : g_kh;
            const void* gp = src + ((size_t)bh * Tv + kv0 + r) * 64 + c * 8;
            uint32_t d = sb + (uint32_t)stg * 18432u + (uint32_t)tile * 9216u
                       + (uint32_t)(r * 144 + c * 16);
            CP_ASYNC(d, gp);
        }
        CP_COMMIT();
    };
    issueKV(0, 0);
    issueKV(1, 1);

    for (int jt = 0; jt < ntl; jt++) {
        if (jt + 1 < ntl) CP_WAIT1(); else CP_WAIT0();
        __syncthreads();                        // tile jt ready; stage (jt-1)%3 drained
        if (jt + 2 < ntl) issueKV(jt + 2, (jt + 2) % 3);
        const int kv0 = jt * 64;
        const uint32_t stg = sb + (uint32_t)(jt % 3) * 18432u;

        if (kv0 <= qb + 15) {
            // ---- S = q * k (1-term fp16) ----
            float s[8][4] = {};
            #pragma unroll
            for (int ks = 0; ks < 4; ks++) {
                #pragma unroll
                for (int p = 0; p < 4; p++) {
                    uint32_t th[4];
                    uint32_t koff = (uint32_t)(
                        (p * 16 + (lane & 7) + ((lane >> 4) & 1) * 8) * 144
                        + (ks * 16 + ((lane >> 3) & 1) * 8) * 2);
                    ldm_x4(th, stg + koff);
                    mma16816(s[2*p],   qh[ks], th);
                    mma16816(s[2*p+1], qh[ks], th + 2);
                }
            }
            // ---- causal mask ----
            const int row0 = qb + g, row1 = row0 + 8;
            if (kv0 + 63 > row0) {
                #pragma unroll
                for (int nt = 0; nt < 8; nt++) {
                    int c0 = kv0 + nt * 8 + tig * 2;
                    if (c0     > row0) s[nt][0] = -1e30f;
                    if (c0 + 1 > row0) s[nt][1] = -1e30f;
                    if (c0     > row1) s[nt][2] = -1e30f;
                    if (c0 + 1 > row1) s[nt][3] = -1e30f;
                }
            }
            // ---- online softmax ----
            float mx0 = -1e30f, mx1 = -1e30f;
            #pragma unroll
            for (int nt = 0; nt < 8; nt++) {
                mx0 = fmaxf(mx0, fmaxf(s[nt][0], s[nt][1]));
                mx1 = fmaxf(mx1, fmaxf(s[nt][2], s[nt][3]));
            }
            mx0 = fmaxf(mx0, __shfl_xor_sync(0xffffffffu, mx0, 1));
            mx0 = fmaxf(mx0, __shfl_xor_sync(0xffffffffu, mx0, 2));
            mx1 = fmaxf(mx1, __shfl_xor_sync(0xffffffffu, mx1, 1));
            mx1 = fmaxf(mx1, __shfl_xor_sync(0xffffffffu, mx1, 2));
            const float mn0 = fmaxf(m0, mx0), mn1 = fmaxf(m1, mx1);
            const float f0 = __expf(m0 - mn0), f1 = __expf(m1 - mn1);
            m0 = mn0; m1 = mn1;

            uint32_t phi[8][2];
            float rs0 = 0.0f, rs1 = 0.0f;
            #pragma unroll
            for (int nt = 0; nt < 8; nt++) {
                float p0 = __expf(s[nt][0] - mn0);
                float p1 = __expf(s[nt][1] - mn0);
                float p2 = __expf(s[nt][2] - mn1);
                float p3 = __expf(s[nt][3] - mn1);
                rs0 += p0 + p1; rs1 += p2 + p3;
                __half2 t01 = __floats2half2_rn(p0, p1);
                __half2 t23 = __floats2half2_rn(p2, p3);
                phi[nt][0] = *(uint32_t*)&t01;
                phi[nt][1] = *(uint32_t*)&t23;
            }
            rs0 += __shfl_xor_sync(0xffffffffu, rs0, 1);
            rs0 += __shfl_xor_sync(0xffffffffu, rs0, 2);
            rs1 += __shfl_xor_sync(0xffffffffu, rs1, 1);
            rs1 += __shfl_xor_sync(0xffffffffu, rs1, 2);
            l0 = l0 * f0 + rs0;
            l1 = l1 * f1 + rs1;
            #pragma unroll
            for (int dt = 0; dt < 8; dt++) {
                acc[dt][0] *= f0; acc[dt][1] *= f0;
                acc[dt][2] *= f1; acc[dt][3] *= f1;
            }
            // ---- O += P V (1-term) ----
            #pragma unroll
            for (int ks = 0; ks < 4; ks++) {
                uint32_t ah[4] = { phi[2*ks][0], phi[2*ks][1], phi[2*ks+1][0], phi[2*ks+1][1] };
                #pragma unroll
                for (int dp = 0; dp < 4; dp++) {
                    uint32_t vh[4];
                    uint32_t voff = (uint32_t)(
                        (ks * 16 + (lane & 7) + ((lane >> 3) & 1) * 8) * 144
                        + (dp * 16 + (lane >> 4) * 8) * 2);
                    ldm_x4t(vh, stg + 9216u + voff);
                    mma16816(acc[2*dp],   ah, vh);
                    mma16816(acc[2*dp+1], ah, vh + 2);
                }
            }
        }
    }

    // ---- epilogue: combo fp16 ----
    const float inv0 = 1.0f / l0, inv1 = 1.0f / l1;
    const int b = bh >> 4, h = bh & 15;
    const int t0 = qb + g, t1 = t0 + 8;
    #pragma unroll
    for (int dt = 0; dt < 8; dt++) {
        const int col = h * 64 + dt * 8 + tig * 2;
        *(__half2*)&g_ch[((size_t)b * Tv + t0) * Cv + col] =
            __floats2half2_rn(acc[dt][0] * inv0, acc[dt][1] * inv0);
        *(__half2*)&g_ch[((size_t)b * Tv + t1) * Cv + col] =
            __floats2half2_rn(acc[dt][2] * inv1, acc[dt][3] * inv1);
    }
}

// ---------------------------------------------------------------------------
extern "C" void kernel_launch(void* const* d_in, const int* in_sizes, int n_in,
                              void* d_out, int out_size)
{
    const float* x  = (const float*)d_in[0];
    const float* Wq = (const float*)d_in[1];
    const float* Wk = (const float*)d_in[2];
    const float* Wv = (const float*)d_in[3];
    const float* Wp = (const float*)d_in[4];
    const float* bp = (const float*)d_in[5];
    float* out = (float*)d_out;

    __half *xh, *wp;
    cudaGetSymbolAddress((void**)&xh, g_xh);
    cudaGetSymbolAddress((void**)&wp, g_wp);

    const int gemm_smem = 3 * 36864;   // 110592 B
    cudaFuncSetAttribute(gemm_kernel<0>, cudaFuncAttributeMaxDynamicSharedMemorySize, gemm_smem);
    cudaFuncSetAttribute(gemm_kernel<1>, cudaFuncAttributeMaxDynamicSharedMemorySize, gemm_smem);
    const int fl_smem = 3 * 18432;     // 55296 B
    cudaFuncSetAttribute(flash_kernel, cudaFuncAttributeMaxDynamicSharedMemorySize, fl_smem);

    // 1. truncate x, Wproj; transpose+truncate Wq/k/v (Wq pre-scaled)
    trunc_kernel<<<(Mv * Cv / 4 + 255) / 256, 256>>>(x, xh, Mv * Cv / 4);
    trunc_kernel<<<(Cv * Cv / 4 + 255) / 256, 256>>>(Wp, wp, Cv * Cv / 4);
    wtrans_kernel<<<dim3(Cv / 64, Hv, 3), 256>>>(Wq, Wk, Wv);

    // 2. QKV projections (1-term, 3-stage, frag double-buffered)
    gemm_kernel<0><<<dim3(Cv / 128, Mv / 128, 3), 256, gemm_smem>>>(nullptr, nullptr);

    // 3. flash attention (all 1-term, 3-stage KV ring) -> combo fp16
    flash_kernel<<<dim3(Tv / 128, Bv * Hv), 256, fl_smem>>>();

    // 4. output projection (1-term, 3-stage, frag double-buffered) + bias
    gemm_kernel<1><<<dim3(Cv / 128, Mv / 128, 1), 256, gemm_smem>>>(bp, out);
}

// round 15
// speedup vs baseline: 1.1550x; 1.1550x over previous
#include <cuda_runtime.h>
#include <cuda_fp16.h>
#include <stdint.h>

#define Bv 4
#define Tv 2048
#define Cv 1024
#define Hv 16
#define HSv 64
#define Mv (Bv*Tv)   /* 8192 */
#define NC 16        /* K=1024 / BK=64 */

// ---------------------------------------------------------------------------
// Static device scratch (no runtime allocation) — all 1-term fp16
// ---------------------------------------------------------------------------
__device__ __half g_xh[(size_t)Mv*Cv];                 // x fp16
__device__ __half g_ch[(size_t)Mv*Cv];                 // combo fp16
__device__ __half g_wt[(size_t)3*Hv*HSv*Cv];           // W^T fp16 (mat0 pre-scaled)
__device__ __half g_wp[(size_t)Cv*Cv];                 // Wproj fp16
__device__ __half g_qh[(size_t)Bv*Hv*Tv*HSv];
__device__ __half g_kh[(size_t)Bv*Hv*Tv*HSv];
__device__ __half g_vh[(size_t)Bv*Hv*Tv*HSv];

// ---------------------------------------------------------------------------
// Helpers
// ---------------------------------------------------------------------------
__device__ __forceinline__ uint32_t smem_u32(const void* p) {
    uint32_t a;
    asm("{ .reg .u64 t; cvta.to.shared.u64 t, %1; cvt.u32.u64 %0, t; }" : "=r"(a) : "l"(p));
    return a;
}
__device__ __forceinline__ void ldm_x4(uint32_t* r, uint32_t a) {
    asm volatile("ldmatrix.sync.aligned.m8n8.x4.shared.b16 {%0,%1,%2,%3}, [%4];"
        : "=r"(r[0]), "=r"(r[1]), "=r"(r[2]), "=r"(r[3]) : "r"(a));
}
__device__ __forceinline__ void ldm_x4t(uint32_t* r, uint32_t a) {
    asm volatile("ldmatrix.sync.aligned.m8n8.x4.trans.shared.b16 {%0,%1,%2,%3}, [%4];"
        : "=r"(r[0]), "=r"(r[1]), "=r"(r[2]), "=r"(r[3]) : "r"(a));
}
__device__ __forceinline__ void mma16816(float* d, const uint32_t* a, const uint32_t* b) {
    asm volatile(
        "mma.sync.aligned.m16n8k16.row.col.f32.f16.f16.f32 "
        "{%0,%1,%2,%3}, {%4,%5,%6,%7}, {%8,%9}, {%0,%1,%2,%3};"
        : "+f"(d[0]), "+f"(d[1]), "+f"(d[2]), "+f"(d[3])
        : "r"(a[0]), "r"(a[1]), "r"(a[2]), "r"(a[3]), "r"(b[0]), "r"(b[1]));
}
#define CP_ASYNC(dst, src) \
    asm volatile("cp.async.cg.shared.global [%0], [%1], 16;" :: "r"(dst), "l"(src) : "memory")
#define CP_COMMIT() asm volatile("cp.async.commit_group;" ::: "memory")
#define CP_WAIT1()  asm volatile("cp.async.wait_group 1;" ::: "memory")
#define CP_WAIT0()  asm volatile("cp.async.wait_group 0;" ::: "memory")

// ---------------------------------------------------------------------------
// Truncate fp32 -> fp16
// ---------------------------------------------------------------------------
__global__ void trunc_kernel(const float* __restrict__ src, __half* __restrict__ dst, int n4)
{
    int i = blockIdx.x * blockDim.x + threadIdx.x;
    if (i >= n4) return;
    float4 v = ((const float4*)src)[i];
    __half2* dp = (__half2*)dst;
    dp[2*i]   = __floats2half2_rn(v.x, v.y);
    dp[2*i+1] = __floats2half2_rn(v.z, v.w);
}

// ---------------------------------------------------------------------------
// Transpose + truncate Wq/Wk/Wv: W[h][c][d] -> Wt[mat][h][d][c]  (fp16)
// Wq pre-scaled by 0.125.
// ---------------------------------------------------------------------------
__global__ __launch_bounds__(256) void wtrans_kernel(
    const float* __restrict__ Wq, const float* __restrict__ Wk, const float* __restrict__ Wv)
{
    __shared__ float ts[64][65];
    const int c0 = blockIdx.x * 64;
    const int h  = blockIdx.y;
    const int mat = blockIdx.z;
    const float* W = (mat == 0) ? Wq : (mat == 1 ? Wk : Wv);
    const float scl = (mat == 0) ? 0.125f : 1.0f;
    const int tid = threadIdx.x;

    #pragma unroll
    for (int i = 0; i < 16; i++) {
        int idx = tid + i * 256;
        int r = idx >> 6, d = idx & 63;
        ts[r][d] = W[(size_t)h * (Cv * HSv) + (size_t)(c0 + r) * HSv + d] * scl;
    }
    __syncthreads();
    #pragma unroll
    for (int i = 0; i < 16; i++) {
        int idx = tid + i * 256;
        int dd = idx >> 6, cc = idx & 63;
        g_wt[((size_t)(mat * Hv + h) * HSv + dd) * Cv + c0 + cc] = __float2half_rn(ts[cc][dd]);
    }
}

// ---------------------------------------------------------------------------
// fp16 1-term GEMM on mma.sync (R12 config — best measured).
// MODE 0: QKV -> q/k/v fp16 (b,h,t,d).   MODE 1: proj -> fp32 out + bias.
// CTA 128x128, BK=64, 4 warps (2x2), warp tile 64x64, 3-stage cp.async.
// ---------------------------------------------------------------------------
template<int MODE>
__global__ __launch_bounds__(128, 2) void gemm_kernel(const float* __restrict__ bias,
                                                      float* __restrict__ outp)
{
    extern __shared__ char smem[];
    const uint32_t sb = smem_u32(smem);
    const int tid = threadIdx.x, lane = tid & 31, wid = tid >> 5;
    const int wm = wid & 1, wn = wid >> 1;         // 2x2 warp grid
    const int nb = blockIdx.x, m0 = blockIdx.y * 128, mat = blockIdx.z;

    const __half *am, *bm;
    if (MODE == 0) {
        am = g_xh;
        bm = g_wt + (size_t)mat * (Hv * HSv * Cv);
    } else {
        am = g_ch;
        bm = g_wp;
    }

    auto issue = [&](int c, int stg) {
        const int kc0 = c * 64;
        const uint32_t sbase = sb + (uint32_t)stg * 36864u;
        #pragma unroll
        for (int i = 0; i < 16; i++) {
            int s = tid + i * 128;
            int ms = s >> 10, r = (s >> 3) & 127, c8 = s & 7;
            const __half* src = ms ? bm : am;
            int row = (ms ? nb * 128 : m0) + r;
            const void* g = src + (size_t)row * Cv + kc0 + c8 * 8;
            uint32_t d = sbase + (uint32_t)ms * 18432u + (uint32_t)(r * 144 + c8 * 16);
            CP_ASYNC(d, g);
        }
        CP_COMMIT();
    };

    issue(0, 0);
    issue(1, 1);
    issue(2, 2);

    float acc[4][8][4] = {};   // [mt 16-row][nt 8-col][frag]

    for (int c = 0; c < NC; c++) {
        if (c + 2 < NC) { asm volatile("cp.async.wait_group 2;" ::: "memory"); }
        else if (c + 1 < NC) CP_WAIT1(); else CP_WAIT0();
        __syncthreads();
        const uint32_t stg = sb + (uint32_t)(c % 3) * 36864u;

        #pragma unroll
        for (int ks = 0; ks < 4; ks++) {
            uint32_t a_[4][4], b_[4][4];
            const int arow = (lane & 7) + ((lane >> 3) & 1) * 8;
            const int acol = ks * 16 + (lane >> 4) * 8;
            #pragma unroll
            for (int mt = 0; mt < 4; mt++) {
                uint32_t off = (uint32_t)((wm * 64 + mt * 16 + arow) * 144 + acol * 2);
                ldm_x4(a_[mt], stg + off);
            }
            #pragma unroll
            for (int ntp = 0; ntp < 4; ntp++) {
                uint32_t off = (uint32_t)(
                    (wn * 64 + ntp * 16 + (lane & 7) + ((lane >> 4) & 1) * 8) * 144
                    + (ks * 16 + ((lane >> 3) & 1) * 8) * 2);
                ldm_x4(b_[ntp], stg + 18432u + off);
            }
            #pragma unroll
            for (int mt = 0; mt < 4; mt++)
                #pragma unroll
                for (int ntp = 0; ntp < 4; ntp++) {
                    mma16816(acc[mt][2*ntp],   a_[mt], b_[ntp]);
                    mma16816(acc[mt][2*ntp+1], a_[mt], b_[ntp] + 2);
                }
        }
        __syncthreads();
        if (c + 3 < NC) issue(c + 3, c % 3);
    }

    const int g = lane >> 2, tig = lane & 3;
    #pragma unroll
    for (int mt = 0; mt < 4; mt++) {
        const int r0 = m0 + wm * 64 + mt * 16 + g;
        const int r1 = r0 + 8;
        #pragma unroll
        for (int nt = 0; nt < 8; nt++) {
            const int n = nb * 128 + wn * 64 + nt * 8 + tig * 2;
            if (MODE == 0) {
                const int h = n >> 6, dd = n & 63;
                int b0 = r0 >> 11, t0 = r0 & (Tv - 1);
                int b1 = r1 >> 11, t1 = r1 & (Tv - 1);
                size_t i0 = (((size_t)(b0 * Hv + h)) * Tv + t0) * HSv + dd;
                size_t i1 = (((size_t)(b1 * Hv + h)) * Tv + t1) * HSv + dd;
                __half* dst = (mat == 0) ? g_qh : (mat == 1) ? g_kh : g_vh;
                *(__half2*)&dst[i0] = __floats2half2_rn(acc[mt][nt][0], acc[mt][nt][1]);
                *(__half2*)&dst[i1] = __floats2half2_rn(acc[mt][nt][2], acc[mt][nt][3]);
            } else {
                float2 bv = *(const float2*)&bias[n];
                *(float2*)&outp[(size_t)r0 * Cv + n] =
                    make_float2(acc[mt][nt][0] + bv.x, acc[mt][nt][1] + bv.y);
                *(float2*)&outp[(size_t)r1 * Cv + n] =
                    make_float2(acc[mt][nt][2] + bv.x, acc[mt][nt][3] + bv.y);
            }
        }
    }
}

// ---------------------------------------------------------------------------
// fp16 HMMA causal flash attention (all 1-term).
// CTA = 128 queries, 8 warps x 16 rows. KV tiles 64, 3-stage cp.async,
// single barrier per tile.  __launch_bounds__(256,2): cap regs at 128 so
// 2 CTAs co-reside per SM (smem 2x55296 = 110.6 KB fits).
// smem: [3 stages][2 tiles: K,V][64 rows x 144B] = 55296 B
// ---------------------------------------------------------------------------
__global__ __launch_bounds__(256, 2) void flash_kernel()
{
    extern __shared__ char smem[];
    const uint32_t sb = smem_u32(smem);
    const int tid = threadIdx.x, lane = tid & 31, w = tid >> 5;
    const int bx = blockIdx.x, bh = blockIdx.y;
    const int q0 = bx * 128;
    const int qb = q0 + w * 16;
    const int g = lane >> 2, tig = lane & 3;

    // ---- stage Q (fp16, 128 rows -> first 18432 B) ----
    {
        #pragma unroll
        for (int i = 0; i < 4; i++) {
            int s = tid + i * 256;
            int r = s >> 3, c = s & 7;
            const void* gp = g_qh + ((size_t)bh * Tv + q0 + r) * 64 + c * 8;
            uint32_t d = sb + (uint32_t)((r >= 64) ? 9216 : 0)
                       + (uint32_t)((r & 63) * 144 + c * 16);
            CP_ASYNC(d, gp);
        }
        CP_COMMIT(); CP_WAIT0();
        __syncthreads();
    }
    uint32_t qh[4][4];
    {
        const int row = w * 16 + (lane & 15);
        const uint32_t hb = sb + ((row >= 64) ? 9216u : 0u);
        const int rl = row & 63;
        #pragma unroll
        for (int ks = 0; ks < 4; ks++) {
            uint32_t off = (uint32_t)(rl * 144 + (ks * 16 + (lane >> 4) * 8) * 2);
            ldm_x4(qh[ks], hb + off);
        }
    }
    __syncthreads();

    float acc[8][4] = {};
    float m0 = -1e30f, m1 = -1e30f, l0 = 0.0f, l1 = 0.0f;
    const int ntl = 2 * bx + 2;

    auto issueKV = [&](int jt, int stg) {
        const int kv0 = jt * 64;
        #pragma unroll
        for (int i = 0; i < 4; i++) {
            int s = tid + i * 256;
            int tile = s >> 9, r = (s >> 3) & 63, c = s & 7;
            const __half* src = tile ? g_vh : g_kh;
            const void* gp = src + ((size_t)bh * Tv + kv0 + r) * 64 + c * 8;
            uint32_t d = sb + (uint32_t)stg * 18432u + (uint32_t)tile * 9216u
                       + (uint32_t)(r * 144 + c * 16);
            CP_ASYNC(d, gp);
        }
        CP_COMMIT();
    };
    issueKV(0, 0);
    issueKV(1, 1);

    for (int jt = 0; jt < ntl; jt++) {
        if (jt + 1 < ntl) CP_WAIT1(); else CP_WAIT0();
        __syncthreads();                        // tile jt ready; stage (jt-1)%3 drained
        if (jt + 2 < ntl) issueKV(jt + 2, (jt + 2) % 3);
        const int kv0 = jt * 64;
        const uint32_t stg = sb + (uint32_t)(jt % 3) * 18432u;

        if (kv0 <= qb + 15) {
            // ---- S = q * k (1-term fp16) ----
            float s[8][4] = {};
            #pragma unroll
            for (int ks = 0; ks < 4; ks++) {
                #pragma unroll
                for (int p = 0; p < 4; p++) {
                    uint32_t th[4];
                    uint32_t koff = (uint32_t)(
                        (p * 16 + (lane & 7) + ((lane >> 4) & 1) * 8) * 144
                        + (ks * 16 + ((lane >> 3) & 1) * 8) * 2);
                    ldm_x4(th, stg + koff);
                    mma16816(s[2*p],   qh[ks], th);
                    mma16816(s[2*p+1], qh[ks], th + 2);
                }
            }
            // ---- causal mask ----
            const int row0 = qb + g, row1 = row0 + 8;
            if (kv0 + 63 > row0) {
                #pragma unroll
                for (int nt = 0; nt < 8; nt++) {
                    int c0 = kv0 + nt * 8 + tig * 2;
                    if (c0     > row0) s[nt][0] = -1e30f;
                    if (c0 + 1 > row0) s[nt][1] = -1e30f;
                    if (c0     > row1) s[nt][2] = -1e30f;
                    if (c0 + 1 > row1) s[nt][3] = -1e30f;
                }
            }
            // ---- online softmax ----
            float mx0 = -1e30f, mx1 = -1e30f;
            #pragma unroll
            for (int nt = 0; nt < 8; nt++) {
                mx0 = fmaxf(mx0, fmaxf(s[nt][0], s[nt][1]));
                mx1 = fmaxf(mx1, fmaxf(s[nt][2], s[nt][3]));
            }
            mx0 = fmaxf(mx0, __shfl_xor_sync(0xffffffffu, mx0, 1));
            mx0 = fmaxf(mx0, __shfl_xor_sync(0xffffffffu, mx0, 2));
            mx1 = fmaxf(mx1, __shfl_xor_sync(0xffffffffu, mx1, 1));
            mx1 = fmaxf(mx1, __shfl_xor_sync(0xffffffffu, mx1, 2));
            const float mn0 = fmaxf(m0, mx0), mn1 = fmaxf(m1, mx1);
            const float f0 = __expf(m0 - mn0), f1 = __expf(m1 - mn1);
            m0 = mn0; m1 = mn1;

            uint32_t phi[8][2];
            float rs0 = 0.0f, rs1 = 0.0f;
            #pragma unroll
            for (int nt = 0; nt < 8; nt++) {
                float p0 = __expf(s[nt][0] - mn0);
                float p1 = __expf(s[nt][1] - mn0);
                float p2 = __expf(s[nt][2] - mn1);
                float p3 = __expf(s[nt][3] - mn1);
                rs0 += p0 + p1; rs1 += p2 + p3;
                __half2 t01 = __floats2half2_rn(p0, p1);
                __half2 t23 = __floats2half2_rn(p2, p3);
                phi[nt][0] = *(uint32_t*)&t01;
                phi[nt][1] = *(uint32_t*)&t23;
            }
            rs0 += __shfl_xor_sync(0xffffffffu, rs0, 1);
            rs0 += __shfl_xor_sync(0xffffffffu, rs0, 2);
            rs1 += __shfl_xor_sync(0xffffffffu, rs1, 1);
            rs1 += __shfl_xor_sync(0xffffffffu, rs1, 2);
            l0 = l0 * f0 + rs0;
            l1 = l1 * f1 + rs1;
            #pragma unroll
            for (int dt = 0; dt < 8; dt++) {
                acc[dt][0] *= f0; acc[dt][1] *= f0;
                acc[dt][2] *= f1; acc[dt][3] *= f1;
            }
            // ---- O += P V (1-term) ----
            #pragma unroll
            for (int ks = 0; ks < 4; ks++) {
                uint32_t ah[4] = { phi[2*ks][0], phi[2*ks][1], phi[2*ks+1][0], phi[2*ks+1][1] };
                #pragma unroll
                for (int dp = 0; dp < 4; dp++) {
                    uint32_t vh[4];
                    uint32_t voff = (uint32_t)(
                        (ks * 16 + (lane & 7) + ((lane >> 3) & 1) * 8) * 144
                        + (dp * 16 + (lane >> 4) * 8) * 2);
                    ldm_x4t(vh, stg + 9216u + voff);
                    mma16816(acc[2*dp],   ah, vh);
                    mma16816(acc[2*dp+1], ah, vh + 2);
                }
            }
        }
    }

    // ---- epilogue: combo fp16 ----
    const float inv0 = 1.0f / l0, inv1 = 1.0f / l1;
    const int b = bh >> 4, h = bh & 15;
    const int t0 = qb + g, t1 = t0 + 8;
    #pragma unroll
    for (int dt = 0; dt < 8; dt++) {
        const int col = h * 64 + dt * 8 + tig * 2;
        *(__half2*)&g_ch[((size_t)b * Tv + t0) * Cv + col] =
            __floats2half2_rn(acc[dt][0] * inv0, acc[dt][1] * inv0);
        *(__half2*)&g_ch[((size_t)b * Tv + t1) * Cv + col] =
            __floats2half2_rn(acc[dt][2] * inv1, acc[dt][3] * inv1);
    }
}

// ---------------------------------------------------------------------------
extern "C" void kernel_launch(void* const* d_in, const int* in_sizes, int n_in,
                              void* d_out, int out_size)
{
    const float* x  = (const float*)d_in[0];
    const float* Wq = (const float*)d_in[1];
    const float* Wk = (const float*)d_in[2];
    const float* Wv = (const float*)d_in[3];
    const float* Wp = (const float*)d_in[4];
    const float* bp = (const float*)d_in[5];
    float* out = (float*)d_out;

    __half *xh, *wp;
    cudaGetSymbolAddress((void**)&xh, g_xh);
    cudaGetSymbolAddress((void**)&wp, g_wp);

    const int gemm_smem = 3 * 36864;   // 110592 B
    cudaFuncSetAttribute(gemm_kernel<0>, cudaFuncAttributeMaxDynamicSharedMemorySize, gemm_smem);
    cudaFuncSetAttribute(gemm_kernel<1>, cudaFuncAttributeMaxDynamicSharedMemorySize, gemm_smem);
    const int fl_smem = 3 * 18432;     // 55296 B
    cudaFuncSetAttribute(flash_kernel, cudaFuncAttributeMaxDynamicSharedMemorySize, fl_smem);

    // 1. truncate x, Wproj; transpose+truncate Wq/k/v (Wq pre-scaled)
    trunc_kernel<<<(Mv * Cv / 4 + 255) / 256, 256>>>(x, xh, Mv * Cv / 4);
    trunc_kernel<<<(Cv * Cv / 4 + 255) / 256, 256>>>(Wp, wp, Cv * Cv / 4);
    wtrans_kernel<<<dim3(Cv / 64, Hv, 3), 256>>>(Wq, Wk, Wv);

    // 2. QKV projections (R12 GEMM config)
    gemm_kernel<0><<<dim3(Cv / 128, Mv / 128, 3), 128, gemm_smem>>>(nullptr, nullptr);

    // 3. flash attention (all 1-term, 3-stage KV ring, occ 2) -> combo fp16
    flash_kernel<<<dim3(Tv / 128, Bv * Hv), 256, fl_smem>>>();

    // 4. output projection + bias
    gemm_kernel<1><<<dim3(Cv / 128, Mv / 128, 1), 128, gemm_smem>>>(bp, out);
}